// round 11
// baseline (speedup 1.0000x reference)
#include <cuda_runtime.h>
#include <cuda_bf16.h>
#include <cstdint>

#define NUM_USERS 20000
#define EMBED_DIM 64
#define KSEL 6          // K+1 = 6 candidates, drop the max, keep 5
#define KNB  5
#define THREADS 256
#define BATCH 4096
#define ROW4 (NUM_USERS / 4)        // 5000 float4 per row
#define STAGE_F4 1024               // float4 per pipeline stage (16 KB)
#define NSTAGE 5                    // 4*1024 + 904 = 5000
#define LAST_F4 (ROW4 - 4 * STAGE_F4)   // 904
#define NBUF 3                      // triple buffer -> prefetch distance 3
#define T_FILT 0.998f               // static filter: E[survivors] ~ 40 of 20000
#define CAP 512

static __device__ __forceinline__ unsigned long long umax64(unsigned long long a,
                                                            unsigned long long b) {
    return a > b ? a : b;
}

static __device__ __forceinline__ unsigned long long pack_key(float f, unsigned idx) {
    return ((unsigned long long)__float_as_uint(f) << 32) | (unsigned)(~idx);
}

static __device__ __forceinline__ uint32_t smem_u32(const void* p) {
    uint32_t a;
    asm("{ .reg .u64 t; cvta.to.shared.u64 t, %1; cvt.u32.u64 %0, t; }"
        : "=r"(a) : "l"(p));
    return a;
}

static __device__ __forceinline__ void mbar_init(uint32_t mbar, uint32_t cnt) {
    asm volatile("mbarrier.init.shared.b64 [%0], %1;" :: "r"(mbar), "r"(cnt) : "memory");
}

static __device__ __forceinline__ void mbar_expect_tx(uint32_t mbar, uint32_t bytes) {
    asm volatile("mbarrier.arrive.expect_tx.shared.b64 _, [%0], %1;"
                 :: "r"(mbar), "r"(bytes) : "memory");
}

static __device__ __forceinline__ void bulk_g2s(uint32_t dst, const void* src,
                                                uint32_t bytes, uint32_t mbar) {
    asm volatile(
        "cp.async.bulk.shared::cta.global.mbarrier::complete_tx::bytes "
        "[%0], [%1], %2, [%3];"
        :: "r"(dst), "l"(src), "r"(bytes), "r"(mbar) : "memory");
}

static __device__ __forceinline__ void mbar_wait(uint32_t mbar, uint32_t parity) {
    uint32_t done;
    asm volatile(
        "{\n\t.reg .pred p;\n\t"
        "mbarrier.try_wait.parity.acquire.cta.shared::cta.b64 p, [%1], %2;\n\t"
        "selp.b32 %0, 1, 0, p;\n\t}"
        : "=r"(done) : "r"(mbar), "r"(parity) : "memory");
    if (!done) {
        asm volatile(
            "{\n\t.reg .pred P1;\n\t"
            "WL_%=:\n\t"
            "mbarrier.try_wait.parity.acquire.cta.shared::cta.b64 P1, [%0], %1, 0x989680;\n\t"
            "@P1 bra.uni WD_%=;\n\t"
            "bra.uni WL_%=;\n\t"
            "WD_%=:\n\t}"
            :: "r"(mbar), "r"(parity) : "memory");
    }
}

// Branchless sorted insert (fallback only). Static indices -> registers.
static __device__ __forceinline__ void insert6(unsigned long long (&top)[KSEL],
                                               unsigned long long key) {
#pragma unroll
    for (int i = 0; i < KSEL; i++) {
        unsigned long long hi = (top[i] > key) ? top[i] : key;
        unsigned long long lo = (top[i] > key) ? key : top[i];
        top[i] = hi;
        key = lo;
    }
}

static __device__ __forceinline__ unsigned long long
block_max64(unsigned long long cand, unsigned long long* warp_max,
            unsigned long long* winner_slot, int tid) {
    unsigned long long m = cand;
#pragma unroll
    for (int off = 16; off > 0; off >>= 1)
        m = umax64(m, __shfl_xor_sync(0xffffffffu, m, off));
    if ((tid & 31) == 0) warp_max[tid >> 5] = m;
    __syncthreads();
    if (tid < 32) {
        unsigned long long mm = (tid < (THREADS / 32)) ? warp_max[tid] : 0ULL;
#pragma unroll
        for (int off = 4; off > 0; off >>= 1)
            mm = umax64(mm, __shfl_xor_sync(0xffffffffu, mm, off));
        if (tid == 0) *winner_slot = mm;
    }
    __syncthreads();
    return *winner_slot;
}

__global__ void __launch_bounds__(THREADS, 4)
topk_blend_kernel(const int* __restrict__ user_idx,
                  const float* __restrict__ emb,
                  const float* __restrict__ cooc,
                  float* __restrict__ out)
{
    __shared__ __align__(128) float4 sbuf[NBUF][STAGE_F4];   // 48 KB triple buffer
    __shared__ __align__(8) unsigned long long mbar[NBUF];
    __shared__ unsigned long long buf[CAP];
    __shared__ unsigned long long warp_max[THREADS / 32];
    __shared__ unsigned long long winners[KSEL];
    __shared__ int cnt;

    const int b   = blockIdx.x;
    const int tid = threadIdx.x;
    const int u   = user_idx[b];

    const float4* row4 = reinterpret_cast<const float4*>(cooc + (size_t)u * NUM_USERS);

    uint32_t mbs[NBUF], sbs[NBUF];
#pragma unroll
    for (int i = 0; i < NBUF; i++) {
        mbs[i] = smem_u32(&mbar[i]);
        sbs[i] = smem_u32(&sbuf[i][0]);
    }

    if (tid == 0) {
        cnt = 0;
#pragma unroll
        for (int i = 0; i < NBUF; i++) mbar_init(mbs[i], 1);
    }
    __syncthreads();

    if (tid == 0) {
#pragma unroll
        for (int i = 0; i < NBUF; i++) {
            mbar_expect_tx(mbs[i], STAGE_F4 * 16);
            bulk_g2s(sbs[i], row4 + i * STAGE_F4, STAGE_F4 * 16, mbs[i]);
        }
    }

    // ---- pass 1: depth-3 pipelined filter out of smem ----
#pragma unroll
    for (int s = 0; s < NSTAGE; s++) {
        const int bi = s % NBUF;
        mbar_wait(mbs[bi], (s / NBUF) & 1);

        const float4* stage = sbuf[bi];
        float4 v[4];
        if (s < NSTAGE - 1) {
#pragma unroll
            for (int j = 0; j < 4; j++)
                v[j] = stage[tid + j * THREADS];
        } else {
#pragma unroll
            for (int j = 0; j < 4; j++) {
                int ii = tid + j * THREADS;
                bool ok = (ii < LAST_F4);
                v[j] = stage[ok ? ii : 0];
                if (!ok) { v[j].x = v[j].y = v[j].z = v[j].w = -1.0f; }
            }
        }

        float m = -1.0f;
#pragma unroll
        for (int j = 0; j < 4; j++)
            m = fmaxf(m, fmaxf(fmaxf(v[j].x, v[j].y), fmaxf(v[j].z, v[j].w)));

        if (m > T_FILT) {
#pragma unroll
            for (int j = 0; j < 4; j++) {
                const unsigned base = (unsigned)((s * STAGE_F4 + tid + j * THREADS) * 4);
#pragma unroll
                for (int c = 0; c < 4; c++) {
                    float f = (c == 0) ? v[j].x : (c == 1) ? v[j].y
                             : (c == 2) ? v[j].z : v[j].w;
                    if (f > T_FILT) {
                        int pos = atomicAdd(&cnt, 1);
                        if (pos < CAP) buf[pos] = pack_key(f, base + c);
                    }
                }
            }
        }

        __syncthreads();   // all reads of sbuf[bi] retired (and stage-s pushes visible)

        if (s + NBUF < NSTAGE && tid == 0) {
            const int ns = s + NBUF;
            const uint32_t bytes = (ns == NSTAGE - 1) ? (LAST_F4 * 16) : (STAGE_F4 * 16);
            mbar_expect_tx(mbs[bi], bytes);
            bulk_g2s(sbs[bi], row4 + ns * STAGE_F4, bytes, mbs[bi]);
        }
    }

    const int n = cnt;   // block-uniform after the last __syncthreads()

    if (n >= KSEL && n <= CAP) {
        // ---- fast selection: 6-round max-reduce with removal ----
        unsigned long long k0 = (tid < n)           ? buf[tid]           : 0ULL;
        unsigned long long k1 = (tid + THREADS < n) ? buf[tid + THREADS] : 0ULL;
#pragma unroll
        for (int r = 0; r < KSEL; r++) {
            unsigned long long w =
                block_max64(umax64(k0, k1), warp_max, &winners[r], tid);
            if (k0 == w)      k0 = 0ULL;   // keys unique (idx embedded)
            else if (k1 == w) k1 = 0ULL;
        }
    } else {
        // ---- exact fallback: full global rescan (cold path) ----
        unsigned long long top[KSEL];
#pragma unroll
        for (int i = 0; i < KSEL; i++) top[i] = 0ULL;
        float thresh = -1.0f;

        for (int i = tid; i < ROW4; i += THREADS) {
            float4 v = row4[i];
            const unsigned base = (unsigned)(i * 4);
            float m = fmaxf(fmaxf(v.x, v.y), fmaxf(v.z, v.w));
            if (m > thresh) {
#pragma unroll
                for (int c = 0; c < 4; c++) {
                    float f = (c == 0) ? v.x : (c == 1) ? v.y : (c == 2) ? v.z : v.w;
                    if (f > thresh) insert6(top, pack_key(f, base + c));
                }
                thresh = __uint_as_float((unsigned)(top[KSEL - 1] >> 32));
            }
        }

        int ptr = 0;
#pragma unroll
        for (int r = 0; r < KSEL; r++) {
            unsigned long long cand;
            switch (ptr) {
                case 0: cand = top[0]; break;
                case 1: cand = top[1]; break;
                case 2: cand = top[2]; break;
                case 3: cand = top[3]; break;
                case 4: cand = top[4]; break;
                case 5: cand = top[5]; break;
                default: cand = 0ULL; break;
            }
            unsigned long long w = block_max64(cand, warp_max, &winners[r], tid);
            if (ptr < KSEL && cand == w) ptr++;
        }
    }

    // ---- epilogue: softmax over winners[1..5], blend embeddings ----
    if (tid < EMBED_DIM) {
        float smax = __uint_as_float((unsigned)(winners[1] >> 32));
        float sum = 0.0f;
        float acc = 0.0f;
#pragma unroll
        for (int j = 0; j < KNB; j++) {
            unsigned long long k = winners[j + 1];
            float    s    = __uint_as_float((unsigned)(k >> 32));
            unsigned sidx = ~(unsigned)(k & 0xffffffffULL);
            float    e    = __expf(s - smax);
            sum += e;
            acc  = fmaf(e, emb[(size_t)sidx * EMBED_DIM + tid], acc);
        }
        float blended = acc / sum;
        out[(size_t)b * EMBED_DIM + tid] =
            fmaf(0.7f, emb[(size_t)u * EMBED_DIM + tid], 0.3f * blended);
    }
}

extern "C" void kernel_launch(void* const* d_in, const int* in_sizes, int n_in,
                              void* d_out, int out_size)
{
    const int*   user_idx = (const int*)d_in[0];
    const float* emb      = (const float*)d_in[1];
    const float* cooc     = (const float*)d_in[2];
    float*       out      = (float*)d_out;

    topk_blend_kernel<<<BATCH, THREADS>>>(user_idx, emb, cooc, out);
}